// round 10
// baseline (speedup 1.0000x reference)
#include <cuda_runtime.h>
#include <cuda_fp16.h>
#include <math.h>
#include <stdint.h>

// ---------------- problem constants ----------------
static constexpr int kIN  = 128;
static constexpr int kH   = 4;
static constexpr int kC   = 64;
static constexpr int kHC  = 256;
static constexpr int kOUT = 512;
static constexpr int MAXN  = 50000;
static constexpr int MAXET = 850000;

// ---------------- scratch ----------------
__device__ float g_bufA[(size_t)MAXN * kHC];
__device__ float g_bufB[(size_t)MAXN * kHC];
__device__ float g_bufC[(size_t)MAXN * kHC];
__device__ float g_attn[6 * (size_t)MAXN * kH];
__device__ int   g_rowptr[MAXN + 1];
__device__ int   g_deg[2 * MAXN];        // [0,N): histogram, [N,2N): fill cursor
__device__ int   g_adj[MAXET];
__device__ int   g_bsum[256];

// ---------------- helpers ----------------
__device__ __forceinline__ uint32_t pack_half2(float x, float y) {
    __half2 h = __float22half2_rn(make_float2(x, y));
    return *(uint32_t*)&h;
}

__device__ __forceinline__ void mma_f16_16x8x16(float* c, const uint32_t* a, const uint32_t* b) {
    asm volatile(
        "mma.sync.aligned.m16n8k16.row.col.f32.f16.f16.f32 "
        "{%0,%1,%2,%3}, {%4,%5,%6,%7}, {%8,%9}, {%0,%1,%2,%3};"
        : "+f"(c[0]), "+f"(c[1]), "+f"(c[2]), "+f"(c[3])
        : "r"(a[0]), "r"(a[1]), "r"(a[2]), "r"(a[3]), "r"(b[0]), "r"(b[1]));
}

// ---------------- fp16 mma.sync GEMM with fused attn epilogue ----------------
// C[rows rowOff.., cols] = A @ W; 128 x BN tile per CTA, BK=32 halves.
template <int BN, int AH, bool HIN, bool HOUT>
__global__ __launch_bounds__(256)
void tgemm_kernel(const void* __restrict__ Ain, const float* __restrict__ W,
                  void* __restrict__ Cout, int M, int K, int Nc, int rowOff,
                  const float* __restrict__ bias, int do_relu,
                  const float* __restrict__ avs, const float* __restrict__ avd,
                  float* __restrict__ as_n, float* __restrict__ ad_n)
{
    static constexpr int SAW = 20;
    static constexpr int SBW = BN + 4;
    static constexpr int NT  = BN / 32;
    static constexpr int NB2 = BN / 16;
    static constexpr int LOG2BN = (BN == 128) ? 7 : 6;

    __shared__ uint32_t sA[128 * SAW];
    __shared__ uint32_t sB[16 * SBW];

    const int tid = threadIdx.x;
    const int wid = tid >> 5;
    const int lid = tid & 31;
    const int g   = lid >> 2;
    const int tig = lid & 3;
    const int warp_m = wid & 1;
    const int warp_n = wid >> 1;

    const int rowBase = blockIdx.y * 128 + rowOff;
    const int colBase = blockIdx.x * BN;

    float acc[4][NT][4];
#pragma unroll
    for (int mt = 0; mt < 4; mt++)
#pragma unroll
        for (int nt = 0; nt < NT; nt++)
#pragma unroll
            for (int i = 0; i < 4; i++) acc[mt][nt][i] = 0.f;

    float4 aRegF[4];
    uint4  aRegH[2];
    float2 wReg[NB2];

    auto loadA = [&](int k0) {
        if (HIN) {
            const __half* A = (const __half*)Ain;
#pragma unroll
            for (int i = 0; i < 2; i++) {
                int idx = tid + 256 * i;
                int m = idx >> 2, c8 = idx & 3;
                int gr = rowBase + m;
                aRegH[i] = (gr < M) ? *(const uint4*)(A + (size_t)gr * K + k0 + c8 * 8)
                                    : make_uint4(0u, 0u, 0u, 0u);
            }
        } else {
            const float* A = (const float*)Ain;
#pragma unroll
            for (int i = 0; i < 4; i++) {
                int idx = tid + 256 * i;
                int m = idx >> 3, c4 = idx & 7;
                int gr = rowBase + m;
                aRegF[i] = (gr < M) ? *(const float4*)(A + (size_t)gr * K + k0 + c4 * 4)
                                    : make_float4(0.f, 0.f, 0.f, 0.f);
            }
        }
    };
    auto loadW = [&](int k0) {
#pragma unroll
        for (int i = 0; i < NB2; i++) {
            int idx = tid + 256 * i;
            int n  = idx & (BN - 1);
            int k2 = idx >> LOG2BN;
            wReg[i].x = W[(size_t)(k0 + 2 * k2)     * Nc + colBase + n];
            wReg[i].y = W[(size_t)(k0 + 2 * k2 + 1) * Nc + colBase + n];
        }
    };
    auto stsTiles = [&]() {
        if (HIN) {
#pragma unroll
            for (int i = 0; i < 2; i++) {
                int idx = tid + 256 * i;
                int m = idx >> 2, c8 = idx & 3;
                *(uint4*)(sA + m * SAW + c8 * 4) = aRegH[i];
            }
        } else {
#pragma unroll
            for (int i = 0; i < 4; i++) {
                int idx = tid + 256 * i;
                int m = idx >> 3, c4 = idx & 7;
                float4 v = aRegF[i];
                uint2 w;
                w.x = pack_half2(v.x, v.y);
                w.y = pack_half2(v.z, v.w);
                *(uint2*)(sA + m * SAW + c4 * 2) = w;
            }
        }
#pragma unroll
        for (int i = 0; i < NB2; i++) {
            int idx = tid + 256 * i;
            int n  = idx & (BN - 1);
            int k2 = idx >> LOG2BN;
            sB[k2 * SBW + n] = pack_half2(wReg[i].x, wReg[i].y);
        }
    };

    const int nchunk = K / 32;
    loadA(0);
    loadW(0);

    for (int ch = 0; ch < nchunk; ch++) {
        stsTiles();
        __syncthreads();
        if (ch + 1 < nchunk) { loadA((ch + 1) * 32); loadW((ch + 1) * 32); }

#pragma unroll
        for (int kk = 0; kk < 2; kk++) {
            const int kb2 = kk * 8;
            uint32_t afr[4][4];
#pragma unroll
            for (int mt = 0; mt < 4; mt++) {
                int m = warp_m * 64 + mt * 16 + g;
                afr[mt][0] = sA[(m)     * SAW + kb2 + tig];
                afr[mt][1] = sA[(m + 8) * SAW + kb2 + tig];
                afr[mt][2] = sA[(m)     * SAW + kb2 + tig + 4];
                afr[mt][3] = sA[(m + 8) * SAW + kb2 + tig + 4];
            }
            uint32_t bfr[NT][2];
#pragma unroll
            for (int nt = 0; nt < NT; nt++) {
                int n = warp_n * (BN / 4) + nt * 8 + g;
                bfr[nt][0] = sB[(kb2 + tig)     * SBW + n];
                bfr[nt][1] = sB[(kb2 + tig + 4) * SBW + n];
            }
#pragma unroll
            for (int mt = 0; mt < 4; mt++)
#pragma unroll
                for (int nt = 0; nt < NT; nt++)
                    mma_f16_16x8x16(acc[mt][nt], afr[mt], bfr[nt]);
        }
        __syncthreads();
    }

    if (AH > 0) {
        const int h = (AH == 1) ? 0 : ((colBase + warp_n * (BN / 4)) >> 6);
#pragma unroll
        for (int mt = 0; mt < 4; mt++) {
            float s0 = 0.f, s1 = 0.f, d0 = 0.f, d1 = 0.f;
#pragma unroll
            for (int nt = 0; nt < NT; nt++) {
                int col = colBase + warp_n * (BN / 4) + nt * 8 + tig * 2;
                float a0 = avs[col], a1 = avs[col + 1];
                float b0 = avd[col], b1 = avd[col + 1];
                s0 += acc[mt][nt][0] * a0 + acc[mt][nt][1] * a1;
                s1 += acc[mt][nt][2] * a0 + acc[mt][nt][3] * a1;
                d0 += acc[mt][nt][0] * b0 + acc[mt][nt][1] * b1;
                d1 += acc[mt][nt][2] * b0 + acc[mt][nt][3] * b1;
            }
#pragma unroll
            for (int off = 1; off <= 2; off <<= 1) {
                s0 += __shfl_xor_sync(0xFFFFFFFFu, s0, off);
                s1 += __shfl_xor_sync(0xFFFFFFFFu, s1, off);
                d0 += __shfl_xor_sync(0xFFFFFFFFu, d0, off);
                d1 += __shfl_xor_sync(0xFFFFFFFFu, d1, off);
            }
            if (tig == 0) {
                int row0 = rowBase + warp_m * 64 + mt * 16 + g;
                int row1 = row0 + 8;
                if (row0 < M) {
                    atomicAdd(&as_n[(size_t)row0 * AH + h], s0);
                    atomicAdd(&ad_n[(size_t)row0 * AH + h], d0);
                }
                if (row1 < M) {
                    atomicAdd(&as_n[(size_t)row1 * AH + h], s1);
                    atomicAdd(&ad_n[(size_t)row1 * AH + h], d1);
                }
            }
        }
    }

#pragma unroll
    for (int mt = 0; mt < 4; mt++) {
        int row0 = rowBase + warp_m * 64 + mt * 16 + g;
        int row1 = row0 + 8;
#pragma unroll
        for (int nt = 0; nt < NT; nt++) {
            int col = colBase + warp_n * (BN / 4) + nt * 8 + tig * 2;
            float bx = 0.f, by = 0.f;
            if (bias) { bx = bias[col]; by = bias[col + 1]; }
            float2 v0 = make_float2(acc[mt][nt][0] + bx, acc[mt][nt][1] + by);
            float2 v1 = make_float2(acc[mt][nt][2] + bx, acc[mt][nt][3] + by);
            if (do_relu) {
                v0.x = fmaxf(v0.x, 0.f); v0.y = fmaxf(v0.y, 0.f);
                v1.x = fmaxf(v1.x, 0.f); v1.y = fmaxf(v1.y, 0.f);
            }
            if (HOUT) {
                __half2* Ch = (__half2*)Cout;
                if (row0 < M) Ch[((size_t)row0 * Nc + col) >> 1] = __float22half2_rn(v0);
                if (row1 < M) Ch[((size_t)row1 * Nc + col) >> 1] = __float22half2_rn(v1);
            } else {
                float* Cf = (float*)Cout;
                if (row0 < M) *(float2*)(Cf + (size_t)row0 * Nc + col) = v0;
                if (row1 < M) *(float2*)(Cf + (size_t)row1 * Nc + col) = v1;
            }
        }
    }
}

// ---------------- CSR build ----------------
__global__ void count_kernel(const int* __restrict__ ei, int E, int N, int* __restrict__ deg)
{
    int e = blockIdx.x * blockDim.x + threadIdx.x;
    int ET = E + N;
    if (e >= ET) return;
    int d = (e < E) ? ei[E + e] : (e - E);
    atomicAdd(&deg[d], 1);
}

__global__ void scan1_kernel(const int* __restrict__ deg, int* __restrict__ rowptr,
                             int* __restrict__ bsum, int N)
{
    __shared__ int sh[1024];
    int i = blockIdx.x * 1024 + threadIdx.x;
    int v = (i < N) ? deg[i] : 0;
    sh[threadIdx.x] = v;
    __syncthreads();
#pragma unroll
    for (int off = 1; off < 1024; off <<= 1) {
        int t = (threadIdx.x >= off) ? sh[threadIdx.x - off] : 0;
        __syncthreads();
        sh[threadIdx.x] += t;
        __syncthreads();
    }
    if (i < N) rowptr[i + 1] = sh[threadIdx.x];
    if (threadIdx.x == 1023) bsum[blockIdx.x] = sh[1023];
}

// scan3 with folded block-sum prefix (49 blocks -> cheap redundant loop)
__global__ void scan3_kernel(int* __restrict__ rowptr, const int* __restrict__ bsum, int N)
{
    int off = 0;
    for (int b = 0; b < blockIdx.x; b++) off += bsum[b];
    int i = blockIdx.x * 1024 + threadIdx.x;
    if (i < N) rowptr[i + 1] += off;
    if (i == 0) rowptr[0] = 0;
}

__global__ void fill_kernel(const int* __restrict__ ei, int E, int N,
                            const int* __restrict__ rowptr, int* __restrict__ cur,
                            int* __restrict__ adj)
{
    int e = blockIdx.x * blockDim.x + threadIdx.x;
    int ET = E + N;
    if (e >= ET) return;
    int s, d;
    if (e < E) { s = ei[e]; d = ei[E + e]; } else { s = d = e - E; }
    int pos = rowptr[d] + atomicAdd(&cur[d], 1);
    adj[pos] = s;
}

// ---------------- fused gather (4-way unroll, half in/out, node range [n0,n1)) --------
__device__ __forceinline__ void acc8_half(float* acc, float a, uint4 r)
{
    const __half2* hp = (const __half2*)&r;
#pragma unroll
    for (int i = 0; i < 4; i++) {
        float2 f = __half22float2(hp[i]);
        acc[2 * i]     += a * f.x;
        acc[2 * i + 1] += a * f.y;
    }
}

__device__ __forceinline__ float edge_alpha(float as_v, float ad)
{
    float l = as_v + ad;
    l = (l > 0.f) ? l : 0.2f * l;
    return __expf(l);
}

__global__ __launch_bounds__(256) void gat_gather4_kernel(
    const int* __restrict__ rowptr, const int* __restrict__ adj,
    const __half* __restrict__ xl,
    const float* __restrict__ as_n, const float* __restrict__ ad_n,
    const float* __restrict__ bias, __half* __restrict__ out, int n0, int n1)
{
    int w = n0 + ((blockIdx.x * blockDim.x + threadIdx.x) >> 5);
    int lane = threadIdx.x & 31;
    if (w >= n1) return;

    const int h   = lane >> 3;
    const int col = lane * 8;
    const float ad = ad_n[(size_t)w * 4 + h];

    float acc[8];
#pragma unroll
    for (int i = 0; i < 8; i++) acc[i] = 0.f;
    float den = 0.f;

    const int beg = rowptr[w], end = rowptr[w + 1];
    int j = beg;
    for (; j + 3 < end; j += 4) {
        int s0 = adj[j], s1 = adj[j + 1], s2 = adj[j + 2], s3 = adj[j + 3];
        float a0 = edge_alpha(as_n[(size_t)s0 * 4 + h], ad);
        float a1 = edge_alpha(as_n[(size_t)s1 * 4 + h], ad);
        float a2 = edge_alpha(as_n[(size_t)s2 * 4 + h], ad);
        float a3 = edge_alpha(as_n[(size_t)s3 * 4 + h], ad);
        uint4 r0 = *(const uint4*)(xl + (size_t)s0 * 256 + col);
        uint4 r1 = *(const uint4*)(xl + (size_t)s1 * 256 + col);
        uint4 r2 = *(const uint4*)(xl + (size_t)s2 * 256 + col);
        uint4 r3 = *(const uint4*)(xl + (size_t)s3 * 256 + col);
        den += (a0 + a1) + (a2 + a3);
        acc8_half(acc, a0, r0);
        acc8_half(acc, a1, r1);
        acc8_half(acc, a2, r2);
        acc8_half(acc, a3, r3);
    }
    for (; j < end; j++) {
        int s = adj[j];
        float a = edge_alpha(as_n[(size_t)s * 4 + h], ad);
        uint4 r = *(const uint4*)(xl + (size_t)s * 256 + col);
        den += a;
        acc8_half(acc, a, r);
    }

    float inv = 1.f / (den + 1e-16f);
    __half2 o[4];
#pragma unroll
    for (int i = 0; i < 4; i++) {
        float2 f;
        f.x = fmaxf(acc[2 * i]     * inv + bias[col + 2 * i],     0.f);
        f.y = fmaxf(acc[2 * i + 1] * inv + bias[col + 2 * i + 1], 0.f);
        o[i] = __float22half2_rn(f);
    }
    *(uint4*)(out + (size_t)w * 256 + col) = *(const uint4*)o;
}

__global__ __launch_bounds__(256) void gat_gather1_kernel(
    const int* __restrict__ rowptr, const int* __restrict__ adj,
    const __half* __restrict__ xl,
    const float* __restrict__ as_n, const float* __restrict__ ad_n,
    const float* __restrict__ bias, __half* __restrict__ out, int n0, int n1)
{
    int w = n0 + ((blockIdx.x * blockDim.x + threadIdx.x) >> 5);
    int lane = threadIdx.x & 31;
    if (w >= n1) return;

    const int col = lane * 2;
    const float ad = ad_n[w];

    float acc0 = 0.f, acc1 = 0.f, den = 0.f;

    const int beg = rowptr[w], end = rowptr[w + 1];
    int j = beg;
    for (; j + 3 < end; j += 4) {
        int s0 = adj[j], s1 = adj[j + 1], s2 = adj[j + 2], s3 = adj[j + 3];
        float a0 = edge_alpha(as_n[s0], ad);
        float a1 = edge_alpha(as_n[s1], ad);
        float a2 = edge_alpha(as_n[s2], ad);
        float a3 = edge_alpha(as_n[s3], ad);
        float2 f0 = __half22float2(*(const __half2*)(xl + (size_t)s0 * 64 + col));
        float2 f1 = __half22float2(*(const __half2*)(xl + (size_t)s1 * 64 + col));
        float2 f2 = __half22float2(*(const __half2*)(xl + (size_t)s2 * 64 + col));
        float2 f3 = __half22float2(*(const __half2*)(xl + (size_t)s3 * 64 + col));
        den += (a0 + a1) + (a2 + a3);
        acc0 += a0 * f0.x + a1 * f1.x + a2 * f2.x + a3 * f3.x;
        acc1 += a0 * f0.y + a1 * f1.y + a2 * f2.y + a3 * f3.y;
    }
    for (; j < end; j++) {
        int s = adj[j];
        float a = edge_alpha(as_n[s], ad);
        float2 f = __half22float2(*(const __half2*)(xl + (size_t)s * 64 + col));
        den += a;
        acc0 += a * f.x;
        acc1 += a * f.y;
    }

    float inv = 1.f / (den + 1e-16f);
    float2 f;
    f.x = fmaxf(acc0 * inv + bias[col + 0], 0.f);
    f.y = fmaxf(acc1 * inv + bias[col + 1], 0.f);
    *(__half2*)(out + (size_t)w * 64 + col) = __float22half2_rn(f);
}

// ---------------- host orchestration ----------------
extern "C" void kernel_launch(void* const* d_in, const int* in_sizes, int n_in,
                              void* d_out, int out_size)
{
    const float* x   = (const float*)d_in[0];
    const int*   ei  = (const int*)d_in[1];
    const float* W1  = (const float*)d_in[2];
    const float* as1 = (const float*)d_in[3];
    const float* ad1 = (const float*)d_in[4];
    const float* b1  = (const float*)d_in[5];
    const float* W2  = (const float*)d_in[6];
    const float* as2 = (const float*)d_in[7];
    const float* ad2 = (const float*)d_in[8];
    const float* b2  = (const float*)d_in[9];
    const float* W3  = (const float*)d_in[10];
    const float* as3 = (const float*)d_in[11];
    const float* ad3 = (const float*)d_in[12];
    const float* b3  = (const float*)d_in[13];
    const float* Wfc = (const float*)d_in[14];
    const float* bfc = (const float*)d_in[15];
    float* out = (float*)d_out;

    int N  = in_sizes[0] / kIN;
    int E  = in_sizes[1] / 2;
    int ET = E + N;

    float *bufA, *bufB, *bufC, *attn;
    int *rowptr, *deg, *adj, *bsum;
    cudaGetSymbolAddress((void**)&bufA, g_bufA);
    cudaGetSymbolAddress((void**)&bufB, g_bufB);
    cudaGetSymbolAddress((void**)&bufC, g_bufC);
    cudaGetSymbolAddress((void**)&attn, g_attn);
    cudaGetSymbolAddress((void**)&rowptr, g_rowptr);
    cudaGetSymbolAddress((void**)&deg,    g_deg);
    cudaGetSymbolAddress((void**)&adj,    g_adj);
    cudaGetSymbolAddress((void**)&bsum,   g_bsum);
    int* cur = deg + N;

    size_t NH = (size_t)N * kH;
    float* pas1 = attn;
    float* pad1 = attn + NH;
    float* pas2 = attn + 2 * NH;
    float* pad2 = attn + 3 * NH;
    float* pas3 = attn + 4 * NH;
    float* pad3 = attn + 5 * NH;

    __half* bufAh = (__half*)bufA;
    __half* bufBh = (__half*)bufB;
    __half* bufCh = (__half*)bufC;

    int edgeBlocks = (ET + 255) / 256;
    int scanBlocks = (N + 1023) / 1024;

    // row chunking: c0 = [0, r0), c1 = [r0, N), aligned to 128-row GEMM tiles
    int NBLK = (N + 127) / 128;
    int nb0 = (NBLK + 1) / 2;
    int r0 = nb0 * 128; if (r0 > N) r0 = N;
    int nb1 = NBLK - nb0;
    int gw0 = (r0 + 7) / 8;                 // gather blocks (8 warps each)
    int gw1 = (N - r0 + 7) / 8;

    static cudaStream_t s2 = nullptr;
    static cudaEvent_t evFork = nullptr, evJoin = nullptr;
    static cudaEvent_t eA = nullptr, eB = nullptr, eC = nullptr, eD = nullptr,
                       eE = nullptr, eF = nullptr;
    if (!s2) {
        cudaStreamCreateWithFlags(&s2, cudaStreamNonBlocking);
        cudaEventCreateWithFlags(&evFork, cudaEventDisableTiming);
        cudaEventCreateWithFlags(&evJoin, cudaEventDisableTiming);
        cudaEventCreateWithFlags(&eA, cudaEventDisableTiming);
        cudaEventCreateWithFlags(&eB, cudaEventDisableTiming);
        cudaEventCreateWithFlags(&eC, cudaEventDisableTiming);
        cudaEventCreateWithFlags(&eD, cudaEventDisableTiming);
        cudaEventCreateWithFlags(&eE, cudaEventDisableTiming);
        cudaEventCreateWithFlags(&eF, cudaEventDisableTiming);
    }

    // attn zeroing precedes all GEMM epilogue atomics (main stream)
    cudaMemsetAsync(attn, 0, 6 * NH * sizeof(float));
    cudaEventRecord(evFork, 0);
    cudaStreamWaitEvent(s2, evFork, 0);

    // ---- CSR build on s2 (overlaps GEMM1) ----
    cudaMemsetAsync(deg, 0, 2 * (size_t)N * sizeof(int), s2);
    count_kernel<<<edgeBlocks, 256, 0, s2>>>(ei, E, N, deg);
    scan1_kernel<<<scanBlocks, 1024, 0, s2>>>(deg, rowptr, bsum, N);
    scan3_kernel<<<scanBlocks, 1024, 0, s2>>>(rowptr, bsum, N);
    fill_kernel<<<edgeBlocks, 256, 0, s2>>>(ei, E, N, rowptr, cur, adj);
    cudaEventRecord(evJoin, s2);

    // ---- GEMM1 full: x -> bufA (xl1, half) ----
    tgemm_kernel<128, 4, false, true><<<dim3(2, NBLK), 256>>>(
        x, W1, bufA, N, kIN, kHC, 0, nullptr, 0, as1, ad1, pas1, pad1);
    cudaStreamWaitEvent(0, evJoin, 0);

    // ---- boundary 1: gather1 (bufA -> bufB), GEMM2 (bufB -> bufC) ----
    gat_gather4_kernel<<<gw0, 256>>>(rowptr, adj, bufAh, pas1, pad1, b1, bufBh, 0, r0);
    cudaEventRecord(eA, 0);
    tgemm_kernel<128, 4, true, true><<<dim3(2, nb0), 256>>>(
        bufBh, W2, bufC, N, kHC, kHC, 0, nullptr, 0, as2, ad2, pas2, pad2);

    cudaStreamWaitEvent(s2, eA, 0);
    gat_gather4_kernel<<<gw1, 256, 0, s2>>>(rowptr, adj, bufAh, pas1, pad1, b1, bufBh, r0, N);
    tgemm_kernel<128, 4, true, true><<<dim3(2, nb1), 256, 0, s2>>>(
        bufBh, W2, bufC, N, kHC, kHC, r0, nullptr, 0, as2, ad2, pas2, pad2);
    cudaEventRecord(eB, s2);

    // ---- boundary 2: gather2 (bufC -> bufB), GEMM3 (bufB -> bufA) ----
    cudaStreamWaitEvent(0, eB, 0);
    gat_gather4_kernel<<<gw0, 256>>>(rowptr, adj, bufCh, pas2, pad2, b2, bufBh, 0, r0);
    cudaEventRecord(eC, 0);
    tgemm_kernel<64, 1, true, true><<<dim3(1, nb0), 256>>>(
        bufBh, W3, bufA, N, kHC, kC, 0, nullptr, 0, as3, ad3, pas3, pad3);

    cudaStreamWaitEvent(s2, eC, 0);
    gat_gather4_kernel<<<gw1, 256, 0, s2>>>(rowptr, adj, bufCh, pas2, pad2, b2, bufBh, r0, N);
    tgemm_kernel<64, 1, true, true><<<dim3(1, nb1), 256, 0, s2>>>(
        bufBh, W3, bufA, N, kHC, kC, r0, nullptr, 0, as3, ad3, pas3, pad3);
    cudaEventRecord(eD, s2);

    // ---- boundary 3: gather3 (bufA -> bufC), fc (bufC -> out) ----
    cudaStreamWaitEvent(0, eD, 0);
    gat_gather1_kernel<<<gw0, 256>>>(rowptr, adj, bufAh, pas3, pad3, b3, bufCh, 0, r0);
    cudaEventRecord(eE, 0);
    tgemm_kernel<128, 0, true, false><<<dim3(4, nb0), 256>>>(
        bufCh, Wfc, out, N, kC, kOUT, 0, bfc, 1, nullptr, nullptr, nullptr, nullptr);

    cudaStreamWaitEvent(s2, eE, 0);
    gat_gather1_kernel<<<gw1, 256, 0, s2>>>(rowptr, adj, bufAh, pas3, pad3, b3, bufCh, r0, N);
    tgemm_kernel<128, 0, true, false><<<dim3(4, nb1), 256, 0, s2>>>(
        bufCh, Wfc, out, N, kC, kOUT, r0, bfc, 1, nullptr, nullptr, nullptr, nullptr);
    cudaEventRecord(eF, s2);

    // final join back to the capture stream
    cudaStreamWaitEvent(0, eF, 0);
}

// round 11
// speedup vs baseline: 1.0486x; 1.0486x over previous
#include <cuda_runtime.h>
#include <cuda_fp16.h>
#include <math.h>
#include <stdint.h>

// ---------------- problem constants ----------------
static constexpr int kIN  = 128;
static constexpr int kH   = 4;
static constexpr int kC   = 64;
static constexpr int kHC  = 256;
static constexpr int kOUT = 512;
static constexpr int MAXN  = 50000;
static constexpr int MAXET = 850000;

// ---------------- scratch ----------------
__device__ float g_bufA[(size_t)MAXN * kHC];
__device__ float g_bufB[(size_t)MAXN * kHC];
__device__ float g_bufC[(size_t)MAXN * kHC];
__device__ float g_attn[6 * (size_t)MAXN * kH];
__device__ int   g_rowptr[MAXN + 1];
__device__ int   g_deg[2 * MAXN];        // [0,N): histogram, [N,2N): fill cursor
__device__ int   g_adj[MAXET];
__device__ int   g_bsum[256];

// ---------------- helpers ----------------
__device__ __forceinline__ uint32_t pack_half2(float x, float y) {
    __half2 h = __float22half2_rn(make_float2(x, y));
    return *(uint32_t*)&h;
}

__device__ __forceinline__ void mma_f16_16x8x16(float* c, const uint32_t* a, const uint32_t* b) {
    asm volatile(
        "mma.sync.aligned.m16n8k16.row.col.f32.f16.f16.f32 "
        "{%0,%1,%2,%3}, {%4,%5,%6,%7}, {%8,%9}, {%0,%1,%2,%3};"
        : "+f"(c[0]), "+f"(c[1]), "+f"(c[2]), "+f"(c[3])
        : "r"(a[0]), "r"(a[1]), "r"(a[2]), "r"(a[3]), "r"(b[0]), "r"(b[1]));
}

// ---------------- fp16 mma.sync GEMM with fused attn epilogue ----------------
template <int BN, int AH, bool HIN, bool HOUT>
__global__ __launch_bounds__(256)
void tgemm_kernel(const void* __restrict__ Ain, const float* __restrict__ W,
                  void* __restrict__ Cout, int M, int K, int Nc,
                  const float* __restrict__ bias, int do_relu,
                  const float* __restrict__ avs, const float* __restrict__ avd,
                  float* __restrict__ as_n, float* __restrict__ ad_n)
{
    static constexpr int SAW = 20;
    static constexpr int SBW = BN + 4;
    static constexpr int NT  = BN / 32;
    static constexpr int NB2 = BN / 16;
    static constexpr int LOG2BN = (BN == 128) ? 7 : 6;

    __shared__ uint32_t sA[128 * SAW];
    __shared__ uint32_t sB[16 * SBW];

    const int tid = threadIdx.x;
    const int wid = tid >> 5;
    const int lid = tid & 31;
    const int g   = lid >> 2;
    const int tig = lid & 3;
    const int warp_m = wid & 1;
    const int warp_n = wid >> 1;

    const int rowBase = blockIdx.y * 128;
    const int colBase = blockIdx.x * BN;

    float acc[4][NT][4];
#pragma unroll
    for (int mt = 0; mt < 4; mt++)
#pragma unroll
        for (int nt = 0; nt < NT; nt++)
#pragma unroll
            for (int i = 0; i < 4; i++) acc[mt][nt][i] = 0.f;

    float4 aRegF[4];
    uint4  aRegH[2];
    float2 wReg[NB2];

    auto loadA = [&](int k0) {
        if (HIN) {
            const __half* A = (const __half*)Ain;
#pragma unroll
            for (int i = 0; i < 2; i++) {
                int idx = tid + 256 * i;
                int m = idx >> 2, c8 = idx & 3;
                int gr = rowBase + m;
                aRegH[i] = (gr < M) ? *(const uint4*)(A + (size_t)gr * K + k0 + c8 * 8)
                                    : make_uint4(0u, 0u, 0u, 0u);
            }
        } else {
            const float* A = (const float*)Ain;
#pragma unroll
            for (int i = 0; i < 4; i++) {
                int idx = tid + 256 * i;
                int m = idx >> 3, c4 = idx & 7;
                int gr = rowBase + m;
                aRegF[i] = (gr < M) ? *(const float4*)(A + (size_t)gr * K + k0 + c4 * 4)
                                    : make_float4(0.f, 0.f, 0.f, 0.f);
            }
        }
    };
    auto loadW = [&](int k0) {
#pragma unroll
        for (int i = 0; i < NB2; i++) {
            int idx = tid + 256 * i;
            int n  = idx & (BN - 1);
            int k2 = idx >> LOG2BN;
            wReg[i].x = W[(size_t)(k0 + 2 * k2)     * Nc + colBase + n];
            wReg[i].y = W[(size_t)(k0 + 2 * k2 + 1) * Nc + colBase + n];
        }
    };
    auto stsTiles = [&]() {
        if (HIN) {
#pragma unroll
            for (int i = 0; i < 2; i++) {
                int idx = tid + 256 * i;
                int m = idx >> 2, c8 = idx & 3;
                *(uint4*)(sA + m * SAW + c8 * 4) = aRegH[i];
            }
        } else {
#pragma unroll
            for (int i = 0; i < 4; i++) {
                int idx = tid + 256 * i;
                int m = idx >> 3, c4 = idx & 7;
                float4 v = aRegF[i];
                uint2 w;
                w.x = pack_half2(v.x, v.y);
                w.y = pack_half2(v.z, v.w);
                *(uint2*)(sA + m * SAW + c4 * 2) = w;
            }
        }
#pragma unroll
        for (int i = 0; i < NB2; i++) {
            int idx = tid + 256 * i;
            int n  = idx & (BN - 1);
            int k2 = idx >> LOG2BN;
            sB[k2 * SBW + n] = pack_half2(wReg[i].x, wReg[i].y);
        }
    };

    const int nchunk = K / 32;
    loadA(0);
    loadW(0);

    for (int ch = 0; ch < nchunk; ch++) {
        stsTiles();
        __syncthreads();
        if (ch + 1 < nchunk) { loadA((ch + 1) * 32); loadW((ch + 1) * 32); }

#pragma unroll
        for (int kk = 0; kk < 2; kk++) {
            const int kb2 = kk * 8;
            uint32_t afr[4][4];
#pragma unroll
            for (int mt = 0; mt < 4; mt++) {
                int m = warp_m * 64 + mt * 16 + g;
                afr[mt][0] = sA[(m)     * SAW + kb2 + tig];
                afr[mt][1] = sA[(m + 8) * SAW + kb2 + tig];
                afr[mt][2] = sA[(m)     * SAW + kb2 + tig + 4];
                afr[mt][3] = sA[(m + 8) * SAW + kb2 + tig + 4];
            }
            uint32_t bfr[NT][2];
#pragma unroll
            for (int nt = 0; nt < NT; nt++) {
                int n = warp_n * (BN / 4) + nt * 8 + g;
                bfr[nt][0] = sB[(kb2 + tig)     * SBW + n];
                bfr[nt][1] = sB[(kb2 + tig + 4) * SBW + n];
            }
#pragma unroll
            for (int mt = 0; mt < 4; mt++)
#pragma unroll
                for (int nt = 0; nt < NT; nt++)
                    mma_f16_16x8x16(acc[mt][nt], afr[mt], bfr[nt]);
        }
        __syncthreads();
    }

    if (AH > 0) {
        const int h = (AH == 1) ? 0 : ((colBase + warp_n * (BN / 4)) >> 6);
#pragma unroll
        for (int mt = 0; mt < 4; mt++) {
            float s0 = 0.f, s1 = 0.f, d0 = 0.f, d1 = 0.f;
#pragma unroll
            for (int nt = 0; nt < NT; nt++) {
                int col = colBase + warp_n * (BN / 4) + nt * 8 + tig * 2;
                float a0 = avs[col], a1 = avs[col + 1];
                float b0 = avd[col], b1 = avd[col + 1];
                s0 += acc[mt][nt][0] * a0 + acc[mt][nt][1] * a1;
                s1 += acc[mt][nt][2] * a0 + acc[mt][nt][3] * a1;
                d0 += acc[mt][nt][0] * b0 + acc[mt][nt][1] * b1;
                d1 += acc[mt][nt][2] * b0 + acc[mt][nt][3] * b1;
            }
#pragma unroll
            for (int off = 1; off <= 2; off <<= 1) {
                s0 += __shfl_xor_sync(0xFFFFFFFFu, s0, off);
                s1 += __shfl_xor_sync(0xFFFFFFFFu, s1, off);
                d0 += __shfl_xor_sync(0xFFFFFFFFu, d0, off);
                d1 += __shfl_xor_sync(0xFFFFFFFFu, d1, off);
            }
            if (tig == 0) {
                int row0 = rowBase + warp_m * 64 + mt * 16 + g;
                int row1 = row0 + 8;
                if (row0 < M) {
                    atomicAdd(&as_n[(size_t)row0 * AH + h], s0);
                    atomicAdd(&ad_n[(size_t)row0 * AH + h], d0);
                }
                if (row1 < M) {
                    atomicAdd(&as_n[(size_t)row1 * AH + h], s1);
                    atomicAdd(&ad_n[(size_t)row1 * AH + h], d1);
                }
            }
        }
    }

#pragma unroll
    for (int mt = 0; mt < 4; mt++) {
        int row0 = rowBase + warp_m * 64 + mt * 16 + g;
        int row1 = row0 + 8;
#pragma unroll
        for (int nt = 0; nt < NT; nt++) {
            int col = colBase + warp_n * (BN / 4) + nt * 8 + tig * 2;
            float bx = 0.f, by = 0.f;
            if (bias) { bx = bias[col]; by = bias[col + 1]; }
            float2 v0 = make_float2(acc[mt][nt][0] + bx, acc[mt][nt][1] + by);
            float2 v1 = make_float2(acc[mt][nt][2] + bx, acc[mt][nt][3] + by);
            if (do_relu) {
                v0.x = fmaxf(v0.x, 0.f); v0.y = fmaxf(v0.y, 0.f);
                v1.x = fmaxf(v1.x, 0.f); v1.y = fmaxf(v1.y, 0.f);
            }
            if (HOUT) {
                __half2* Ch = (__half2*)Cout;
                if (row0 < M) Ch[((size_t)row0 * Nc + col) >> 1] = __float22half2_rn(v0);
                if (row1 < M) Ch[((size_t)row1 * Nc + col) >> 1] = __float22half2_rn(v1);
            } else {
                float* Cf = (float*)Cout;
                if (row0 < M) *(float2*)(Cf + (size_t)row0 * Nc + col) = v0;
                if (row1 < M) *(float2*)(Cf + (size_t)row1 * Nc + col) = v1;
            }
        }
    }
}

// ---------------- CSR build (4 edges / thread, int4 loads) ----------------
__global__ void count_kernel(const int* __restrict__ ei, int E, int N, int* __restrict__ deg)
{
    int base = (blockIdx.x * blockDim.x + threadIdx.x) * 4;
    int ET = E + N;
    if (base >= ET) return;
    if (base + 3 < E) {
        int4 d4 = *(const int4*)(ei + E + base);
        atomicAdd(&deg[d4.x], 1);
        atomicAdd(&deg[d4.y], 1);
        atomicAdd(&deg[d4.z], 1);
        atomicAdd(&deg[d4.w], 1);
    } else {
#pragma unroll
        for (int k = 0; k < 4; k++) {
            int e = base + k;
            if (e >= ET) break;
            int d = (e < E) ? ei[E + e] : (e - E);
            atomicAdd(&deg[d], 1);
        }
    }
}

__global__ void scan1_kernel(const int* __restrict__ deg, int* __restrict__ rowptr,
                             int* __restrict__ bsum, int N)
{
    __shared__ int sh[1024];
    int i = blockIdx.x * 1024 + threadIdx.x;
    int v = (i < N) ? deg[i] : 0;
    sh[threadIdx.x] = v;
    __syncthreads();
#pragma unroll
    for (int off = 1; off < 1024; off <<= 1) {
        int t = (threadIdx.x >= off) ? sh[threadIdx.x - off] : 0;
        __syncthreads();
        sh[threadIdx.x] += t;
        __syncthreads();
    }
    if (i < N) rowptr[i + 1] = sh[threadIdx.x];
    if (threadIdx.x == 1023) bsum[blockIdx.x] = sh[1023];
}

// scan3 with folded block-sum prefix (49 blocks -> cheap redundant loop)
__global__ void scan3_kernel(int* __restrict__ rowptr, const int* __restrict__ bsum, int N)
{
    int off = 0;
    for (int b = 0; b < blockIdx.x; b++) off += bsum[b];
    int i = blockIdx.x * 1024 + threadIdx.x;
    if (i < N) rowptr[i + 1] += off;
    if (i == 0) rowptr[0] = 0;
}

__global__ void fill_kernel(const int* __restrict__ ei, int E, int N,
                            const int* __restrict__ rowptr, int* __restrict__ cur,
                            int* __restrict__ adj)
{
    int base = (blockIdx.x * blockDim.x + threadIdx.x) * 4;
    int ET = E + N;
    if (base >= ET) return;
    if (base + 3 < E) {
        int4 s4 = *(const int4*)(ei + base);
        int4 d4 = *(const int4*)(ei + E + base);
        int p0 = rowptr[d4.x] + atomicAdd(&cur[d4.x], 1);
        int p1 = rowptr[d4.y] + atomicAdd(&cur[d4.y], 1);
        int p2 = rowptr[d4.z] + atomicAdd(&cur[d4.z], 1);
        int p3 = rowptr[d4.w] + atomicAdd(&cur[d4.w], 1);
        adj[p0] = s4.x;
        adj[p1] = s4.y;
        adj[p2] = s4.z;
        adj[p3] = s4.w;
    } else {
#pragma unroll
        for (int k = 0; k < 4; k++) {
            int e = base + k;
            if (e >= ET) break;
            int s, d;
            if (e < E) { s = ei[e]; d = ei[E + e]; } else { s = d = e - E; }
            int pos = rowptr[d] + atomicAdd(&cur[d], 1);
            adj[pos] = s;
        }
    }
}

// ---------------- fused gather (4-way unroll, half in/out) ----------------
__device__ __forceinline__ void acc8_half(float* acc, float a, uint4 r)
{
    const __half2* hp = (const __half2*)&r;
#pragma unroll
    for (int i = 0; i < 4; i++) {
        float2 f = __half22float2(hp[i]);
        acc[2 * i]     += a * f.x;
        acc[2 * i + 1] += a * f.y;
    }
}

__device__ __forceinline__ float edge_alpha(float as_v, float ad)
{
    float l = as_v + ad;
    l = (l > 0.f) ? l : 0.2f * l;
    return __expf(l);
}

__global__ __launch_bounds__(256) void gat_gather4_kernel(
    const int* __restrict__ rowptr, const int* __restrict__ adj,
    const __half* __restrict__ xl,
    const float* __restrict__ as_n, const float* __restrict__ ad_n,
    const float* __restrict__ bias, __half* __restrict__ out, int N)
{
    int w = (blockIdx.x * blockDim.x + threadIdx.x) >> 5;
    int lane = threadIdx.x & 31;
    if (w >= N) return;

    const int h   = lane >> 3;
    const int col = lane * 8;
    const float ad = ad_n[(size_t)w * 4 + h];

    float acc[8];
#pragma unroll
    for (int i = 0; i < 8; i++) acc[i] = 0.f;
    float den = 0.f;

    const int beg = rowptr[w], end = rowptr[w + 1];
    int j = beg;
    for (; j + 3 < end; j += 4) {
        int s0 = adj[j], s1 = adj[j + 1], s2 = adj[j + 2], s3 = adj[j + 3];
        float a0 = edge_alpha(as_n[(size_t)s0 * 4 + h], ad);
        float a1 = edge_alpha(as_n[(size_t)s1 * 4 + h], ad);
        float a2 = edge_alpha(as_n[(size_t)s2 * 4 + h], ad);
        float a3 = edge_alpha(as_n[(size_t)s3 * 4 + h], ad);
        uint4 r0 = *(const uint4*)(xl + (size_t)s0 * 256 + col);
        uint4 r1 = *(const uint4*)(xl + (size_t)s1 * 256 + col);
        uint4 r2 = *(const uint4*)(xl + (size_t)s2 * 256 + col);
        uint4 r3 = *(const uint4*)(xl + (size_t)s3 * 256 + col);
        den += (a0 + a1) + (a2 + a3);
        acc8_half(acc, a0, r0);
        acc8_half(acc, a1, r1);
        acc8_half(acc, a2, r2);
        acc8_half(acc, a3, r3);
    }
    for (; j < end; j++) {
        int s = adj[j];
        float a = edge_alpha(as_n[(size_t)s * 4 + h], ad);
        uint4 r = *(const uint4*)(xl + (size_t)s * 256 + col);
        den += a;
        acc8_half(acc, a, r);
    }

    float inv = 1.f / (den + 1e-16f);
    __half2 o[4];
#pragma unroll
    for (int i = 0; i < 4; i++) {
        float2 f;
        f.x = fmaxf(acc[2 * i]     * inv + bias[col + 2 * i],     0.f);
        f.y = fmaxf(acc[2 * i + 1] * inv + bias[col + 2 * i + 1], 0.f);
        o[i] = __float22half2_rn(f);
    }
    *(uint4*)(out + (size_t)w * 256 + col) = *(const uint4*)o;
}

__global__ __launch_bounds__(256) void gat_gather1_kernel(
    const int* __restrict__ rowptr, const int* __restrict__ adj,
    const __half* __restrict__ xl,
    const float* __restrict__ as_n, const float* __restrict__ ad_n,
    const float* __restrict__ bias, __half* __restrict__ out, int N)
{
    int w = (blockIdx.x * blockDim.x + threadIdx.x) >> 5;
    int lane = threadIdx.x & 31;
    if (w >= N) return;

    const int col = lane * 2;
    const float ad = ad_n[w];

    float acc0 = 0.f, acc1 = 0.f, den = 0.f;

    const int beg = rowptr[w], end = rowptr[w + 1];
    int j = beg;
    for (; j + 3 < end; j += 4) {
        int s0 = adj[j], s1 = adj[j + 1], s2 = adj[j + 2], s3 = adj[j + 3];
        float a0 = edge_alpha(as_n[s0], ad);
        float a1 = edge_alpha(as_n[s1], ad);
        float a2 = edge_alpha(as_n[s2], ad);
        float a3 = edge_alpha(as_n[s3], ad);
        float2 f0 = __half22float2(*(const __half2*)(xl + (size_t)s0 * 64 + col));
        float2 f1 = __half22float2(*(const __half2*)(xl + (size_t)s1 * 64 + col));
        float2 f2 = __half22float2(*(const __half2*)(xl + (size_t)s2 * 64 + col));
        float2 f3 = __half22float2(*(const __half2*)(xl + (size_t)s3 * 64 + col));
        den += (a0 + a1) + (a2 + a3);
        acc0 += a0 * f0.x + a1 * f1.x + a2 * f2.x + a3 * f3.x;
        acc1 += a0 * f0.y + a1 * f1.y + a2 * f2.y + a3 * f3.y;
    }
    for (; j < end; j++) {
        int s = adj[j];
        float a = edge_alpha(as_n[s], ad);
        float2 f = __half22float2(*(const __half2*)(xl + (size_t)s * 64 + col));
        den += a;
        acc0 += a * f.x;
        acc1 += a * f.y;
    }

    float inv = 1.f / (den + 1e-16f);
    float2 f;
    f.x = fmaxf(acc0 * inv + bias[col + 0], 0.f);
    f.y = fmaxf(acc1 * inv + bias[col + 1], 0.f);
    *(__half2*)(out + (size_t)w * 64 + col) = __float22half2_rn(f);
}

// ---------------- host orchestration ----------------
extern "C" void kernel_launch(void* const* d_in, const int* in_sizes, int n_in,
                              void* d_out, int out_size)
{
    const float* x   = (const float*)d_in[0];
    const int*   ei  = (const int*)d_in[1];
    const float* W1  = (const float*)d_in[2];
    const float* as1 = (const float*)d_in[3];
    const float* ad1 = (const float*)d_in[4];
    const float* b1  = (const float*)d_in[5];
    const float* W2  = (const float*)d_in[6];
    const float* as2 = (const float*)d_in[7];
    const float* ad2 = (const float*)d_in[8];
    const float* b2  = (const float*)d_in[9];
    const float* W3  = (const float*)d_in[10];
    const float* as3 = (const float*)d_in[11];
    const float* ad3 = (const float*)d_in[12];
    const float* b3  = (const float*)d_in[13];
    const float* Wfc = (const float*)d_in[14];
    const float* bfc = (const float*)d_in[15];
    float* out = (float*)d_out;

    int N  = in_sizes[0] / kIN;
    int E  = in_sizes[1] / 2;
    int ET = E + N;

    float *bufA, *bufB, *bufC, *attn;
    int *rowptr, *deg, *adj, *bsum;
    cudaGetSymbolAddress((void**)&bufA, g_bufA);
    cudaGetSymbolAddress((void**)&bufB, g_bufB);
    cudaGetSymbolAddress((void**)&bufC, g_bufC);
    cudaGetSymbolAddress((void**)&attn, g_attn);
    cudaGetSymbolAddress((void**)&rowptr, g_rowptr);
    cudaGetSymbolAddress((void**)&deg,    g_deg);
    cudaGetSymbolAddress((void**)&adj,    g_adj);
    cudaGetSymbolAddress((void**)&bsum,   g_bsum);
    int* cur = deg + N;

    size_t NH = (size_t)N * kH;
    float* pas1 = attn;
    float* pad1 = attn + NH;
    float* pas2 = attn + 2 * NH;
    float* pad2 = attn + 3 * NH;
    float* pas3 = attn + 4 * NH;
    float* pad3 = attn + 5 * NH;

    __half* bufAh = (__half*)bufA;
    __half* bufBh = (__half*)bufB;
    __half* bufCh = (__half*)bufC;

    int edge4Blocks = (ET + 1023) / 1024;       // 4 edges per thread
    int nodeWarpBlocks = (N + 7) / 8;
    int scanBlocks = (N + 1023) / 1024;

    dim3 grid256(2, (N + 127) / 128);
    dim3 grid64(1, (N + 127) / 128);
    dim3 gridFC(4, (N + 127) / 128);

    static cudaStream_t s2 = nullptr;
    static cudaEvent_t evFork = nullptr, evJoin = nullptr;
    if (!s2) {
        cudaStreamCreateWithFlags(&s2, cudaStreamNonBlocking);
        cudaEventCreateWithFlags(&evFork, cudaEventDisableTiming);
        cudaEventCreateWithFlags(&evJoin, cudaEventDisableTiming);
    }

    // attn zeroing precedes all GEMM epilogue atomics (main stream)
    cudaMemsetAsync(attn, 0, 6 * NH * sizeof(float));
    cudaEventRecord(evFork, 0);
    cudaStreamWaitEvent(s2, evFork, 0);

    // ---- CSR build on s2 (overlaps GEMM1) ----
    cudaMemsetAsync(deg, 0, 2 * (size_t)N * sizeof(int), s2);
    count_kernel<<<edge4Blocks, 256, 0, s2>>>(ei, E, N, deg);
    scan1_kernel<<<scanBlocks, 1024, 0, s2>>>(deg, rowptr, bsum, N);
    scan3_kernel<<<scanBlocks, 1024, 0, s2>>>(rowptr, bsum, N);
    fill_kernel<<<edge4Blocks, 256, 0, s2>>>(ei, E, N, rowptr, cur, adj);
    cudaEventRecord(evJoin, s2);

    // ---- layer 1 GEMM (independent of CSR) ----
    tgemm_kernel<128, 4, false, true><<<grid256, 256>>>(
        x, W1, bufA, N, kIN, kHC, nullptr, 0, as1, ad1, pas1, pad1);
    cudaStreamWaitEvent(0, evJoin, 0);

    gat_gather4_kernel<<<nodeWarpBlocks, 256>>>(rowptr, adj, bufAh, pas1, pad1, b1, bufBh, N);

    // ---- layer 2 ----
    tgemm_kernel<128, 4, true, true><<<grid256, 256>>>(
        bufBh, W2, bufA, N, kHC, kHC, nullptr, 0, as2, ad2, pas2, pad2);
    gat_gather4_kernel<<<nodeWarpBlocks, 256>>>(rowptr, adj, bufAh, pas2, pad2, b2, bufCh, N);

    // ---- layer 3 ----
    tgemm_kernel<64, 1, true, true><<<grid64, 256>>>(
        bufCh, W3, bufA, N, kHC, kC, nullptr, 0, as3, ad3, pas3, pad3);
    gat_gather1_kernel<<<nodeWarpBlocks, 256>>>(rowptr, adj, bufAh, pas3, pad3, b3, bufBh, N);

    // ---- final fc ----
    tgemm_kernel<128, 0, true, false><<<gridFC, 256>>>(
        bufBh, Wfc, out, N, kC, kOUT, bfc, 1, nullptr, nullptr, nullptr, nullptr);
}